// round 1
// baseline (speedup 1.0000x reference)
#include <cuda_runtime.h>

// ---------------------------------------------------------------------------
// Problem dims
//   x   [256,512,128], W11 [128,128], b11 [128], W12 [384,192], W2 [6,384]
//   out [256,512,6]  float32
// Decomposition:
//   A: fc11 GEMM + dnew epilogue       -> g_dnew  [M,64]
//   B: inclusive prefix-max over T     -> g_dmg   [M,64]
//   C: fc12 GEMM (x ++ dmg)            -> g_strain[M,384]
//   D: plane-stress D-mult + seq       -> g_strain (in place, = sig_tr), g_seq
//   E: per-(b,p) plasticity scan       -> g_scale [M,128]
//   F: fc2 + softplus                  -> out
// ---------------------------------------------------------------------------

typedef unsigned long long u64;

#define MM 131072   // 256*512

__device__ float g_dnew[(size_t)MM * 64];
__device__ float g_dmg[(size_t)MM * 64];
__device__ float g_strain[(size_t)MM * 384];
__device__ float g_seq[(size_t)MM * 128];
__device__ float g_scale[(size_t)MM * 128];

// packed f32x2 helpers (sm_103a FFMA2 path)
__device__ __forceinline__ u64 pk2(float x, float y) {
    u64 r; asm("mov.b64 %0, {%1, %2};" : "=l"(r) : "f"(x), "f"(y)); return r;
}
__device__ __forceinline__ u64 ffma2(u64 a, u64 b, u64 c) {
    u64 d; asm("fma.rn.f32x2 %0, %1, %2, %3;" : "=l"(d) : "l"(a), "l"(b), "l"(c)); return d;
}
__device__ __forceinline__ float2 up2(u64 v) {
    float2 f; asm("mov.b64 {%0, %1}, %2;" : "=f"(f.x), "=f"(f.y) : "l"(v)); return f;
}

// ---------------------------------------------------------------------------
// Kernel A: fc11 GEMM  C[m,n] = sum_k x[m,k]*W11[n,k]   M=131072, N=128, K=128
// Epilogue: +bias, leaky-relu, pairwise Turon dnew -> g_dnew
// Tiling: BM=BN=128, BK=16, 256 threads, 8x8 per thread, f32x2 accumulators.
// ---------------------------------------------------------------------------
__global__ void __launch_bounds__(256, 2) k_fc11(const float* __restrict__ x,
                                                 const float* __restrict__ W11,
                                                 const float* __restrict__ b11)
{
    __shared__ __align__(16) float As[16][132];
    __shared__ __align__(16) float Bs[16][132];
    const int tid = threadIdx.x;
    const int m0  = blockIdx.x << 7;
    const int ar  = tid >> 2;         // 0..63
    const int ac  = (tid & 3) << 2;   // 0,4,8,12
    const int tm0 = (tid >> 4) << 3;
    const int tn0 = (tid & 15) << 3;

    u64 acc[8][4];
#pragma unroll
    for (int i = 0; i < 8; ++i)
#pragma unroll
        for (int j = 0; j < 4; ++j) acc[i][j] = 0ull;

    float4 pa0 = *(const float4*)(x + (size_t)(m0 + ar) * 128 + ac);
    float4 pa1 = *(const float4*)(x + (size_t)(m0 + ar + 64) * 128 + ac);
    float4 pb0 = *(const float4*)(W11 + ar * 128 + ac);
    float4 pb1 = *(const float4*)(W11 + (ar + 64) * 128 + ac);

    for (int kt = 0; kt < 8; ++kt) {
        __syncthreads();
        As[ac+0][ar] = pa0.x; As[ac+1][ar] = pa0.y; As[ac+2][ar] = pa0.z; As[ac+3][ar] = pa0.w;
        As[ac+0][ar+64] = pa1.x; As[ac+1][ar+64] = pa1.y; As[ac+2][ar+64] = pa1.z; As[ac+3][ar+64] = pa1.w;
        Bs[ac+0][ar] = pb0.x; Bs[ac+1][ar] = pb0.y; Bs[ac+2][ar] = pb0.z; Bs[ac+3][ar] = pb0.w;
        Bs[ac+0][ar+64] = pb1.x; Bs[ac+1][ar+64] = pb1.y; Bs[ac+2][ar+64] = pb1.z; Bs[ac+3][ar+64] = pb1.w;
        __syncthreads();
        if (kt < 7) {
            int k1 = (kt + 1) << 4;
            pa0 = *(const float4*)(x + (size_t)(m0 + ar) * 128 + k1 + ac);
            pa1 = *(const float4*)(x + (size_t)(m0 + ar + 64) * 128 + k1 + ac);
            pb0 = *(const float4*)(W11 + ar * 128 + k1 + ac);
            pb1 = *(const float4*)(W11 + (ar + 64) * 128 + k1 + ac);
        }
#pragma unroll
        for (int kk = 0; kk < 16; ++kk) {
            float4 a0 = *(const float4*)&As[kk][tm0];
            float4 a1 = *(const float4*)&As[kk][tm0 + 4];
            float4 b0 = *(const float4*)&Bs[kk][tn0];
            float4 b1 = *(const float4*)&Bs[kk][tn0 + 4];
            u64 bb0 = pk2(b0.x, b0.y), bb1 = pk2(b0.z, b0.w);
            u64 bb2 = pk2(b1.x, b1.y), bb3 = pk2(b1.z, b1.w);
            float av[8] = {a0.x, a0.y, a0.z, a0.w, a1.x, a1.y, a1.z, a1.w};
#pragma unroll
            for (int i = 0; i < 8; ++i) {
                u64 ad = pk2(av[i], av[i]);
                acc[i][0] = ffma2(ad, bb0, acc[i][0]);
                acc[i][1] = ffma2(ad, bb1, acc[i][1]);
                acc[i][2] = ffma2(ad, bb2, acc[i][2]);
                acc[i][3] = ffma2(ad, bb3, acc[i][3]);
            }
        }
    }

    // epilogue: bias + leaky_relu, then dnew per (even,odd) column pair
#pragma unroll
    for (int i = 0; i < 8; ++i) {
        int m = m0 + tm0 + i;
#pragma unroll
        for (int j = 0; j < 4; ++j) {
            float2 v = up2(acc[i][j]);
            int c = tn0 + 2 * j;
            float v0 = v.x + b11[c];
            float v1 = v.y + b11[c + 1];
            v0 = v0 > 0.f ? v0 : 0.01f * v0;   // leaky
            v1 = v1 > 0.f ? v1 : 0.01f * v1;
            float jn = fmaxf(v0, 0.f);         // relu(normal jump)
            float js = v1;
            float delta = sqrtf(jn * jn + js * js + 1e-12f);
            float dn = __fdividef(0.1f * (delta - 0.01f),
                                  fmaxf(delta, 1e-12f) * 0.09f);
            dn = fminf(fmaxf(dn, 0.f), 1.f);
            g_dnew[(size_t)m * 64 + (c >> 1)] = dn;
        }
    }
}

// ---------------------------------------------------------------------------
// Kernel B: inclusive prefix-max of dnew along T (damage never heals).
// one thread per (b,p) chain; 8-wide load batching for MLP.
// ---------------------------------------------------------------------------
__global__ void k_prefixmax()
{
    int t = blockIdx.x * blockDim.x + threadIdx.x;   // 0..16383
    int b = t >> 6, p = t & 63;
    const float* src = g_dnew + (size_t)b * 512 * 64 + p;
    float*       dst = g_dmg  + (size_t)b * 512 * 64 + p;
    float run = 0.f;
    for (int t0 = 0; t0 < 512; t0 += 8) {
        float v[8];
#pragma unroll
        for (int i = 0; i < 8; ++i) v[i] = src[(size_t)(t0 + i) * 64];
#pragma unroll
        for (int i = 0; i < 8; ++i) {
            run = fmaxf(run, v[i]);
            dst[(size_t)(t0 + i) * 64] = run;
        }
    }
}

// ---------------------------------------------------------------------------
// Kernel C: fc12 GEMM  strain[m,n] = sum_k midini[m,k]*W12[n,k]
//   midini = concat(x[m,0:128], dmg[m,0:64]); K=192, N=384.
// ---------------------------------------------------------------------------
__device__ __forceinline__ float4 ldA12(const float* __restrict__ x, int row, int k)
{
    if (k < 128) return *(const float4*)(x + (size_t)row * 128 + k);
    return *(const float4*)(g_dmg + (size_t)row * 64 + (k - 128));
}

__global__ void __launch_bounds__(256, 2) k_fc12(const float* __restrict__ x,
                                                 const float* __restrict__ W12)
{
    __shared__ __align__(16) float As[16][132];
    __shared__ __align__(16) float Bs[16][132];
    const int tid = threadIdx.x;
    const int m0  = blockIdx.x << 7;
    const int n0  = blockIdx.y << 7;
    const int ar  = tid >> 2;
    const int ac  = (tid & 3) << 2;
    const int tm0 = (tid >> 4) << 3;
    const int tn0 = (tid & 15) << 3;

    u64 acc[8][4];
#pragma unroll
    for (int i = 0; i < 8; ++i)
#pragma unroll
        for (int j = 0; j < 4; ++j) acc[i][j] = 0ull;

    float4 pa0 = ldA12(x, m0 + ar, ac);
    float4 pa1 = ldA12(x, m0 + ar + 64, ac);
    float4 pb0 = *(const float4*)(W12 + (size_t)(n0 + ar) * 192 + ac);
    float4 pb1 = *(const float4*)(W12 + (size_t)(n0 + ar + 64) * 192 + ac);

    for (int kt = 0; kt < 12; ++kt) {
        __syncthreads();
        As[ac+0][ar] = pa0.x; As[ac+1][ar] = pa0.y; As[ac+2][ar] = pa0.z; As[ac+3][ar] = pa0.w;
        As[ac+0][ar+64] = pa1.x; As[ac+1][ar+64] = pa1.y; As[ac+2][ar+64] = pa1.z; As[ac+3][ar+64] = pa1.w;
        Bs[ac+0][ar] = pb0.x; Bs[ac+1][ar] = pb0.y; Bs[ac+2][ar] = pb0.z; Bs[ac+3][ar] = pb0.w;
        Bs[ac+0][ar+64] = pb1.x; Bs[ac+1][ar+64] = pb1.y; Bs[ac+2][ar+64] = pb1.z; Bs[ac+3][ar+64] = pb1.w;
        __syncthreads();
        if (kt < 11) {
            int k1 = (kt + 1) << 4;
            pa0 = ldA12(x, m0 + ar, k1 + ac);
            pa1 = ldA12(x, m0 + ar + 64, k1 + ac);
            pb0 = *(const float4*)(W12 + (size_t)(n0 + ar) * 192 + k1 + ac);
            pb1 = *(const float4*)(W12 + (size_t)(n0 + ar + 64) * 192 + k1 + ac);
        }
#pragma unroll
        for (int kk = 0; kk < 16; ++kk) {
            float4 a0 = *(const float4*)&As[kk][tm0];
            float4 a1 = *(const float4*)&As[kk][tm0 + 4];
            float4 b0 = *(const float4*)&Bs[kk][tn0];
            float4 b1 = *(const float4*)&Bs[kk][tn0 + 4];
            u64 bb0 = pk2(b0.x, b0.y), bb1 = pk2(b0.z, b0.w);
            u64 bb2 = pk2(b1.x, b1.y), bb3 = pk2(b1.z, b1.w);
            float av[8] = {a0.x, a0.y, a0.z, a0.w, a1.x, a1.y, a1.z, a1.w};
#pragma unroll
            for (int i = 0; i < 8; ++i) {
                u64 ad = pk2(av[i], av[i]);
                acc[i][0] = ffma2(ad, bb0, acc[i][0]);
                acc[i][1] = ffma2(ad, bb1, acc[i][1]);
                acc[i][2] = ffma2(ad, bb2, acc[i][2]);
                acc[i][3] = ffma2(ad, bb3, acc[i][3]);
            }
        }
    }

#pragma unroll
    for (int i = 0; i < 8; ++i) {
        size_t off = (size_t)(m0 + tm0 + i) * 384 + n0 + tn0;
        float2 v0 = up2(acc[i][0]), v1 = up2(acc[i][1]);
        float2 v2 = up2(acc[i][2]), v3 = up2(acc[i][3]);
        float4 w0 = make_float4(v0.x, v0.y, v1.x, v1.y);
        float4 w1 = make_float4(v2.x, v2.y, v3.x, v3.y);
        *(float4*)(g_strain + off)     = w0;
        *(float4*)(g_strain + off + 4) = w1;
    }
}

// ---------------------------------------------------------------------------
// Kernel D: plane-stress D-multiply (in place: strain -> trial stress) + seq
// ---------------------------------------------------------------------------
__global__ void k_stress()
{
    int idx = blockIdx.x * 256 + threadIdx.x;     // 0 .. M*128-1
    int m = idx >> 7, p = idx & 127;
    float* s = g_strain + (size_t)m * 384 + 3 * p;
    float e0 = s[0], e1 = s[1], e2 = s[2];
    const float C   = (float)(1000.0 / 0.91);
    const float CNU = (float)(1000.0 * 0.3 / 0.91);
    const float CSH = (float)((1000.0 / 0.91) * (0.7 / 2.0));
    float sxx = C * e0 + CNU * e1;
    float syy = CNU * e0 + C * e1;
    float txy = CSH * e2;
    float seq = sqrtf(sxx * sxx - sxx * syy + syy * syy + 3.f * txy * txy + 1e-12f);
    s[0] = sxx; s[1] = syy; s[2] = txy;
    g_seq[(size_t)m * 128 + p] = seq;
}

// ---------------------------------------------------------------------------
// Kernel E: the only true recurrence — J2 radial-return ep chains per (b,p).
// ---------------------------------------------------------------------------
__global__ void k_ep()
{
    int t = blockIdx.x * 256 + threadIdx.x;       // 0..32767
    int b = t >> 7, p = t & 127;
    const float* sq = g_seq   + (size_t)b * 512 * 128 + p;
    float*       sc = g_scale + (size_t)b * 512 * 128 + p;
    const float SY = 10.f, H = 100.f;
    const float INV = (float)(1.0 / (3.0 * (1000.0 / 2.6) + 100.0));
    float ep = 0.f;
#pragma unroll 4
    for (int tt = 0; tt < 512; ++tt) {
        float seq = sq[(size_t)tt * 128];
        float fy = seq - fmaf(H, ep, SY);
        float scale;
        if (fy > 0.f) {
            ep = fmaf(fy, INV, ep);
            scale = __fdividef(fmaf(H, ep, SY), seq);
        } else {
            scale = 1.f;
        }
        sc[(size_t)tt * 128] = scale;
    }
}

// ---------------------------------------------------------------------------
// Kernel F: fc2 + softplus.  out[m,o] = softplus(sum_p scale[p]*sig_tr[3p+i]*W2[o,3p+i])
// one warp per row m.
// ---------------------------------------------------------------------------
__global__ void k_fc2(const float* __restrict__ W2, float* __restrict__ out)
{
    __shared__ float w2s[6 * 384];
    int tid = threadIdx.x;
    for (int i = tid; i < 2304; i += 256) w2s[i] = W2[i];
    __syncthreads();

    int warp = tid >> 5, lane = tid & 31;
    int m = blockIdx.x * 8 + warp;
    const float* sig = g_strain + (size_t)m * 384;
    const float* scl = g_scale  + (size_t)m * 128;
    float acc[6] = {0.f, 0.f, 0.f, 0.f, 0.f, 0.f};
#pragma unroll
    for (int q = 0; q < 4; ++q) {
        int p = lane + 32 * q;
        float s = scl[p];
        float f0 = sig[3 * p], f1 = sig[3 * p + 1], f2 = sig[3 * p + 2];
        float g0 = s * f0, g1 = s * f1, g2 = s * f2;
#pragma unroll
        for (int o = 0; o < 6; ++o) {
            acc[o] = fmaf(g0, w2s[o * 384 + 3 * p],     acc[o]);
            acc[o] = fmaf(g1, w2s[o * 384 + 3 * p + 1], acc[o]);
            acc[o] = fmaf(g2, w2s[o * 384 + 3 * p + 2], acc[o]);
        }
    }
#pragma unroll
    for (int o = 0; o < 6; ++o)
#pragma unroll
        for (int off = 16; off; off >>= 1)
            acc[o] += __shfl_xor_sync(0xffffffffu, acc[o], off);
    if (lane == 0) {
#pragma unroll
        for (int o = 0; o < 6; ++o) {
            float v = acc[o];
            float sp = fmaxf(v, 0.f) + log1pf(expf(-fabsf(v)));
            out[(size_t)m * 6 + o] = sp;
        }
    }
}

// ---------------------------------------------------------------------------
extern "C" void kernel_launch(void* const* d_in, const int* in_sizes, int n_in,
                              void* d_out, int out_size)
{
    const float* x   = (const float*)d_in[0];   // [256,512,128]
    const float* W11 = (const float*)d_in[1];   // [128,128]
    const float* b11 = (const float*)d_in[2];   // [128]
    const float* W12 = (const float*)d_in[3];   // [384,192]
    const float* W2  = (const float*)d_in[4];   // [6,384]
    float* out = (float*)d_out;                 // [256,512,6]

    (void)in_sizes; (void)n_in; (void)out_size;

    k_fc11<<<MM / 128, 256>>>(x, W11, b11);
    k_prefixmax<<<64, 256>>>();
    k_fc12<<<dim3(MM / 128, 3), 256>>>(x, W12);
    k_stress<<<(MM * 128) / 256, 256>>>();
    k_ep<<<128, 256>>>();
    k_fc2<<<MM / 8, 256>>>(W2, out);
}

// round 3
// speedup vs baseline: 1.2948x; 1.2948x over previous
#include <cuda_runtime.h>
#include <cuda_bf16.h>
#include <cstdint>

// ---------------------------------------------------------------------------
// Pipeline:
//   A: fc11 FFMA2 GEMM + dnew epilogue      -> g_dnew  [M,64]
//   B: prefix-max over T                    -> g_dmg   [M,64]
//   P: fold plane-stress D into W12, bf16 hi/lo split -> g_Bp [384,576] bf16
//   C: fc12 mma.sync bf16-split GEMM (K'=576) + seq epilogue
//        -> g_strain (= trial stress sig_tr) [M,384], g_seq [M,128]
//   E: J2 plasticity scan                   -> g_scale [M,128]
//   F: fc2 + softplus                       -> out
// ---------------------------------------------------------------------------

typedef unsigned long long u64;

#define MM 131072   // 256*512

__device__ float g_dnew[(size_t)MM * 64];
__device__ float g_dmg[(size_t)MM * 64];
__device__ float g_strain[(size_t)MM * 384];
__device__ float g_seq[(size_t)MM * 128];
__device__ float g_scale[(size_t)MM * 128];
__device__ __nv_bfloat16 g_Bp[384 * 576];

// packed f32x2 helpers (FFMA2 path for fc11)
__device__ __forceinline__ u64 pk2(float x, float y) {
    u64 r; asm("mov.b64 %0, {%1, %2};" : "=l"(r) : "f"(x), "f"(y)); return r;
}
__device__ __forceinline__ u64 ffma2(u64 a, u64 b, u64 c) {
    u64 d; asm("fma.rn.f32x2 %0, %1, %2, %3;" : "=l"(d) : "l"(a), "l"(b), "l"(c)); return d;
}
__device__ __forceinline__ float2 up2(u64 v) {
    float2 f; asm("mov.b64 {%0, %1}, %2;" : "=f"(f.x), "=f"(f.y) : "l"(v)); return f;
}

// ---------------------------------------------------------------------------
// Kernel A: fc11 GEMM (FFMA2) + dnew epilogue
// ---------------------------------------------------------------------------
__global__ void __launch_bounds__(256, 2) k_fc11(const float* __restrict__ x,
                                                 const float* __restrict__ W11,
                                                 const float* __restrict__ b11)
{
    __shared__ __align__(16) float As[16][132];
    __shared__ __align__(16) float Bs[16][132];
    const int tid = threadIdx.x;
    const int m0  = blockIdx.x << 7;
    const int ar  = tid >> 2;
    const int ac  = (tid & 3) << 2;
    const int tm0 = (tid >> 4) << 3;
    const int tn0 = (tid & 15) << 3;

    u64 acc[8][4];
#pragma unroll
    for (int i = 0; i < 8; ++i)
#pragma unroll
        for (int j = 0; j < 4; ++j) acc[i][j] = 0ull;

    float4 pa0 = *(const float4*)(x + (size_t)(m0 + ar) * 128 + ac);
    float4 pa1 = *(const float4*)(x + (size_t)(m0 + ar + 64) * 128 + ac);
    float4 pb0 = *(const float4*)(W11 + ar * 128 + ac);
    float4 pb1 = *(const float4*)(W11 + (ar + 64) * 128 + ac);

    for (int kt = 0; kt < 8; ++kt) {
        __syncthreads();
        As[ac+0][ar] = pa0.x; As[ac+1][ar] = pa0.y; As[ac+2][ar] = pa0.z; As[ac+3][ar] = pa0.w;
        As[ac+0][ar+64] = pa1.x; As[ac+1][ar+64] = pa1.y; As[ac+2][ar+64] = pa1.z; As[ac+3][ar+64] = pa1.w;
        Bs[ac+0][ar] = pb0.x; Bs[ac+1][ar] = pb0.y; Bs[ac+2][ar] = pb0.z; Bs[ac+3][ar] = pb0.w;
        Bs[ac+0][ar+64] = pb1.x; Bs[ac+1][ar+64] = pb1.y; Bs[ac+2][ar+64] = pb1.z; Bs[ac+3][ar+64] = pb1.w;
        __syncthreads();
        if (kt < 7) {
            int k1 = (kt + 1) << 4;
            pa0 = *(const float4*)(x + (size_t)(m0 + ar) * 128 + k1 + ac);
            pa1 = *(const float4*)(x + (size_t)(m0 + ar + 64) * 128 + k1 + ac);
            pb0 = *(const float4*)(W11 + ar * 128 + k1 + ac);
            pb1 = *(const float4*)(W11 + (ar + 64) * 128 + k1 + ac);
        }
#pragma unroll
        for (int kk = 0; kk < 16; ++kk) {
            float4 a0 = *(const float4*)&As[kk][tm0];
            float4 a1 = *(const float4*)&As[kk][tm0 + 4];
            float4 b0 = *(const float4*)&Bs[kk][tn0];
            float4 b1 = *(const float4*)&Bs[kk][tn0 + 4];
            u64 bb0 = pk2(b0.x, b0.y), bb1 = pk2(b0.z, b0.w);
            u64 bb2 = pk2(b1.x, b1.y), bb3 = pk2(b1.z, b1.w);
            float av[8] = {a0.x, a0.y, a0.z, a0.w, a1.x, a1.y, a1.z, a1.w};
#pragma unroll
            for (int i = 0; i < 8; ++i) {
                u64 ad = pk2(av[i], av[i]);
                acc[i][0] = ffma2(ad, bb0, acc[i][0]);
                acc[i][1] = ffma2(ad, bb1, acc[i][1]);
                acc[i][2] = ffma2(ad, bb2, acc[i][2]);
                acc[i][3] = ffma2(ad, bb3, acc[i][3]);
            }
        }
    }

#pragma unroll
    for (int i = 0; i < 8; ++i) {
        int m = m0 + tm0 + i;
#pragma unroll
        for (int j = 0; j < 4; ++j) {
            float2 v = up2(acc[i][j]);
            int c = tn0 + 2 * j;
            float v0 = v.x + b11[c];
            float v1 = v.y + b11[c + 1];
            v0 = v0 > 0.f ? v0 : 0.01f * v0;
            v1 = v1 > 0.f ? v1 : 0.01f * v1;
            float jn = fmaxf(v0, 0.f);
            float js = v1;
            float delta = sqrtf(jn * jn + js * js + 1e-12f);
            float dn = __fdividef(0.1f * (delta - 0.01f),
                                  fmaxf(delta, 1e-12f) * 0.09f);
            dn = fminf(fmaxf(dn, 0.f), 1.f);
            g_dnew[(size_t)m * 64 + (c >> 1)] = dn;
        }
    }
}

// ---------------------------------------------------------------------------
// Kernel B: inclusive prefix-max of dnew along T
// ---------------------------------------------------------------------------
__global__ void k_prefixmax()
{
    int t = blockIdx.x * blockDim.x + threadIdx.x;
    int b = t >> 6, p = t & 63;
    const float* src = g_dnew + (size_t)b * 512 * 64 + p;
    float*       dst = g_dmg  + (size_t)b * 512 * 64 + p;
    float run = 0.f;
    for (int t0 = 0; t0 < 512; t0 += 8) {
        float v[8];
#pragma unroll
        for (int i = 0; i < 8; ++i) v[i] = src[(size_t)(t0 + i) * 64];
#pragma unroll
        for (int i = 0; i < 8; ++i) {
            run = fmaxf(run, v[i]);
            dst[(size_t)(t0 + i) * 64] = run;
        }
    }
}

// ---------------------------------------------------------------------------
// Kernel P: fold plane-stress D into W12 and build bf16 split B' [384,576]:
//   cols [0,192)=hi(B) (pairs hi_A), [192,384)=hi(B) (pairs lo_A),
//   cols [384,576)=lo(B) (pairs hi_A)
// ---------------------------------------------------------------------------
__global__ void k_prepB(const float* __restrict__ W12)
{
    int t = blockIdx.x * 256 + threadIdx.x;
    if (t >= 384 * 192) return;
    int n = t / 192, k = t % 192;
    int p3 = (n / 3) * 3, j = n % 3;
    const float C   = 1098.9010989010989f;   // E/(1-nu^2)
    const float CNU = 329.67032967032966f;   // C*nu
    const float CSH = 384.61538461538464f;   // C*(1-nu)/2
    float w;
    if (j == 0)      w = C   * W12[(size_t)p3 * 192 + k] + CNU * W12[(size_t)(p3 + 1) * 192 + k];
    else if (j == 1) w = CNU * W12[(size_t)p3 * 192 + k] + C   * W12[(size_t)(p3 + 1) * 192 + k];
    else             w = CSH * W12[(size_t)n * 192 + k];
    __nv_bfloat16 hi = __float2bfloat16(w);
    float lo = w - __bfloat162float(hi);
    g_Bp[(size_t)n * 576 + k]       = hi;
    g_Bp[(size_t)n * 576 + 192 + k] = hi;
    g_Bp[(size_t)n * 576 + 384 + k] = __float2bfloat16(lo);
}

// ---------------------------------------------------------------------------
// Kernel C: fc12 via legacy tensor path mma.sync.m16n8k16 (bf16, f32 acc).
//   grid (1024, 2): BM=128 rows, BN=192 cols of C (N total = 384).
//   K' = 576 (bf16 split), Kc=32 per stage, double-buffered SMEM.
//   256 threads = 8 warps, warp grid 4(M) x 2(N): warp tile 32x96.
//   Epilogue: acc -> SMEM slab -> seq + coalesced sig_tr/seq stores.
// ---------------------------------------------------------------------------
#define APITCH 80   // bytes per SMEM row (32 bf16 = 64B data + 16B pad)

__device__ __forceinline__ uint32_t smem_u32(const void* p) {
    uint32_t a;
    asm("{ .reg .u64 t; cvta.to.shared.u64 t, %1; cvt.u32.u64 %0, t; }" : "=r"(a) : "l"(p));
    return a;
}
__device__ __forceinline__ void ldsm_x4(uint32_t& r0, uint32_t& r1, uint32_t& r2,
                                        uint32_t& r3, uint32_t addr) {
    asm volatile("ldmatrix.sync.aligned.m8n8.x4.shared.b16 {%0,%1,%2,%3}, [%4];"
                 : "=r"(r0), "=r"(r1), "=r"(r2), "=r"(r3) : "r"(addr));
}
__device__ __forceinline__ void mma16816(float& c0, float& c1, float& c2, float& c3,
                                         uint32_t a0, uint32_t a1, uint32_t a2, uint32_t a3,
                                         uint32_t b0, uint32_t b1) {
    asm volatile("mma.sync.aligned.m16n8k16.row.col.f32.bf16.bf16.f32 "
                 "{%0,%1,%2,%3}, {%4,%5,%6,%7}, {%8,%9}, {%0,%1,%2,%3};"
                 : "+f"(c0), "+f"(c1), "+f"(c2), "+f"(c3)
                 : "r"(a0), "r"(a1), "r"(a2), "r"(a3), "r"(b0), "r"(b1));
}

// dynamic SMEM: stage buffers: buf0 A@0 (128*80), B@10240 (192*80);
//               buf1 A@40960, B@51200.  Epilogue slabs: warp w @ w*12800 (32x100 f32)
#define FC12_SMEM 102400

__global__ void __launch_bounds__(256, 1) k_fc12_mma(const float* __restrict__ x)
{
    extern __shared__ char smem[];
    const uint32_t sb = smem_u32(smem);
    const int tid  = threadIdx.x;
    const int lane = tid & 31;
    const int w    = tid >> 5;          // 0..7
    const int wm   = w >> 1;            // 0..3
    const int wn   = w & 1;             // 0..1
    const int g    = lane >> 2;         // group id
    const int t4   = lane & 3;
    const int m0   = blockIdx.x << 7;
    const int gy   = blockIdx.y;        // n-tile: cols gy*192..

    float acc[2][12][4];
#pragma unroll
    for (int a = 0; a < 2; ++a)
#pragma unroll
        for (int b = 0; b < 12; ++b)
#pragma unroll
            for (int c = 0; c < 4; ++c) acc[a][b][c] = 0.f;

    // A-load mapping: id = tid + i*256 -> r=id>>3 (0..127), c4=id&7 (4-float chunk)
    const int ar = tid >> 3, ac4 = tid & 7;
    // B-load mapping: id = tid + i*256 -> r=id>>2 (0..191), c16=id&3 (16B chunk)
    const int br = tid >> 2, bc16 = tid & 3;

    float4 pa[4];
    uint4  pb[3];

    // prefetch stage 0
    {
        const int s = 0;
        const int kk0 = (s % 6) << 5;
#pragma unroll
        for (int i = 0; i < 4; ++i) {
            int r = ar + (i << 5);
            int col = kk0 + (ac4 << 2);
            const float* src = (col < 128)
                ? (x + (size_t)(m0 + r) * 128 + col)
                : (g_dmg + (size_t)(m0 + r) * 64 + (col - 128));
            pa[i] = *(const float4*)src;
        }
#pragma unroll
        for (int i = 0; i < 3; ++i) {
            int r = br + (i << 6);
            pb[i] = *(const uint4*)(g_Bp + (size_t)(gy * 192 + r) * 576 + (bc16 << 3));
        }
    }

    for (int s = 0; s < 18; ++s) {
        const int buf = s & 1;
        const bool lo_mode = (s >= 6 && s < 12);
        const uint32_t Ab = sb + (buf ? 40960u : 0u);
        const uint32_t Bb = sb + (buf ? 51200u : 10240u);

        __syncthreads();   // prior users of this buffer are done

        // store A (fp32 -> bf16 hi/lo)
        {
            char* Abase = smem + (buf ? 40960 : 0);
#pragma unroll
            for (int i = 0; i < 4; ++i) {
                int r = ar + (i << 5);
                float fx = pa[i].x, fy = pa[i].y, fz = pa[i].z, fw = pa[i].w;
                if (lo_mode) {
                    fx -= __bfloat162float(__float2bfloat16(fx));
                    fy -= __bfloat162float(__float2bfloat16(fy));
                    fz -= __bfloat162float(__float2bfloat16(fz));
                    fw -= __bfloat162float(__float2bfloat16(fw));
                }
                __nv_bfloat162 p0 = __floats2bfloat162_rn(fx, fy);
                __nv_bfloat162 p1 = __floats2bfloat162_rn(fz, fw);
                uint32_t u0 = *(uint32_t*)&p0;
                uint32_t u1 = *(uint32_t*)&p1;
                *(u64*)(Abase + r * APITCH + (ac4 << 3)) = (u64)u0 | ((u64)u1 << 32);
            }
            char* Bbase = smem + (buf ? 51200 : 10240);
#pragma unroll
            for (int i = 0; i < 3; ++i) {
                int r = br + (i << 6);
                *(uint4*)(Bbase + r * APITCH + (bc16 << 4)) = pb[i];
            }
        }
        __syncthreads();

        // prefetch next stage
        if (s < 17) {
            const int sn = s + 1;
            const int kk0 = (sn % 6) << 5;
#pragma unroll
            for (int i = 0; i < 4; ++i) {
                int r = ar + (i << 5);
                int col = kk0 + (ac4 << 2);
                const float* src = (col < 128)
                    ? (x + (size_t)(m0 + r) * 128 + col)
                    : (g_dmg + (size_t)(m0 + r) * 64 + (col - 128));
                pa[i] = *(const float4*)src;
            }
#pragma unroll
            for (int i = 0; i < 3; ++i) {
                int r = br + (i << 6);
                pb[i] = *(const uint4*)(g_Bp + (size_t)(gy * 192 + r) * 576
                                        + (size_t)sn * 32 + (bc16 << 3));
            }
        }

        // compute: 2 k16 steps
#pragma unroll
        for (int ks = 0; ks < 2; ++ks) {
            const int kk = ks << 4;
            uint32_t a[2][4];
#pragma unroll
            for (int mt = 0; mt < 2; ++mt) {
                int row = wm * 32 + mt * 16 + (lane & 15);
                uint32_t addr = Ab + row * APITCH + ((kk + ((lane >> 4) << 3)) << 1);
                ldsm_x4(a[mt][0], a[mt][1], a[mt][2], a[mt][3], addr);
            }
#pragma unroll
            for (int np = 0; np < 6; ++np) {
                int n = wn * 96 + np * 16 + ((lane >> 4) << 3) + (lane & 7);
                uint32_t addr = Bb + n * APITCH + ((kk + (lane & 8)) << 1);
                uint32_t b0, b1, b2, b3;
                ldsm_x4(b0, b1, b2, b3, addr);
#pragma unroll
                for (int mt = 0; mt < 2; ++mt) {
                    mma16816(acc[mt][2*np][0], acc[mt][2*np][1], acc[mt][2*np][2], acc[mt][2*np][3],
                             a[mt][0], a[mt][1], a[mt][2], a[mt][3], b0, b1);
                    mma16816(acc[mt][2*np+1][0], acc[mt][2*np+1][1], acc[mt][2*np+1][2], acc[mt][2*np+1][3],
                             a[mt][0], a[mt][1], a[mt][2], a[mt][3], b2, b3);
                }
            }
        }
    }

    // ---------------- epilogue: acc -> slab -> seq + stores ----------------
    __syncthreads();   // all compute done before overwriting smem with C slabs
    float* slab = (float*)smem + w * 3200;     // 32 x 100 floats
#pragma unroll
    for (int mt = 0; mt < 2; ++mt)
#pragma unroll
        for (int nn = 0; nn < 12; ++nn) {
            int row = mt * 16 + g;
            int col = nn * 8 + 2 * t4;
            slab[row * 100 + col]           = acc[mt][nn][0];
            slab[row * 100 + col + 1]       = acc[mt][nn][1];
            slab[(row + 8) * 100 + col]     = acc[mt][nn][2];
            slab[(row + 8) * 100 + col + 1] = acc[mt][nn][3];
        }
    __syncwarp();

    const int mbase = m0 + wm * 32;
    const int cb = gy * 192 + wn * 96;
    const int pbi = gy * 64 + wn * 32;
#pragma unroll 1
    for (int r = 0; r < 32; ++r) {
        float s0 = slab[r * 100 + 3 * lane];
        float s1 = slab[r * 100 + 3 * lane + 1];
        float s2 = slab[r * 100 + 3 * lane + 2];
        float seq = sqrtf(s0 * s0 - s0 * s1 + s1 * s1 + 3.f * s2 * s2 + 1e-12f);
        g_seq[(size_t)(mbase + r) * 128 + pbi + lane] = seq;
        if (lane < 24) {
            float4 v = *(float4*)&slab[r * 100 + 4 * lane];
            *(float4*)&g_strain[(size_t)(mbase + r) * 384 + cb + 4 * lane] = v;
        }
    }
}

// ---------------------------------------------------------------------------
// Kernel E: J2 radial-return ep chains (the only true recurrence)
// ---------------------------------------------------------------------------
__global__ void k_ep()
{
    int t = blockIdx.x * 256 + threadIdx.x;
    int b = t >> 7, p = t & 127;
    const float* sq = g_seq   + (size_t)b * 512 * 128 + p;
    float*       sc = g_scale + (size_t)b * 512 * 128 + p;
    const float SY = 10.f, H = 100.f;
    const float INV = (float)(1.0 / (3.0 * (1000.0 / 2.6) + 100.0));
    float ep = 0.f;
#pragma unroll 4
    for (int tt = 0; tt < 512; ++tt) {
        float seq = sq[(size_t)tt * 128];
        float fy = seq - fmaf(H, ep, SY);
        float scale;
        if (fy > 0.f) {
            ep = fmaf(fy, INV, ep);
            scale = __fdividef(fmaf(H, ep, SY), seq);
        } else {
            scale = 1.f;
        }
        sc[(size_t)tt * 128] = scale;
    }
}

// ---------------------------------------------------------------------------
// Kernel F: fc2 + softplus
// ---------------------------------------------------------------------------
__global__ void k_fc2(const float* __restrict__ W2, float* __restrict__ out)
{
    __shared__ float w2s[6 * 384];
    int tid = threadIdx.x;
    for (int i = tid; i < 2304; i += 256) w2s[i] = W2[i];
    __syncthreads();

    int warp = tid >> 5, lane = tid & 31;
    int m = blockIdx.x * 8 + warp;
    const float* sig = g_strain + (size_t)m * 384;
    const float* scl = g_scale  + (size_t)m * 128;
    float acc[6] = {0.f, 0.f, 0.f, 0.f, 0.f, 0.f};
#pragma unroll
    for (int q = 0; q < 4; ++q) {
        int p = lane + 32 * q;
        float s = scl[p];
        float f0 = sig[3 * p], f1 = sig[3 * p + 1], f2 = sig[3 * p + 2];
        float g0 = s * f0, g1 = s * f1, g2 = s * f2;
#pragma unroll
        for (int o = 0; o < 6; ++o) {
            acc[o] = fmaf(g0, w2s[o * 384 + 3 * p],     acc[o]);
            acc[o] = fmaf(g1, w2s[o * 384 + 3 * p + 1], acc[o]);
            acc[o] = fmaf(g2, w2s[o * 384 + 3 * p + 2], acc[o]);
        }
    }
#pragma unroll
    for (int o = 0; o < 6; ++o)
#pragma unroll
        for (int off = 16; off; off >>= 1)
            acc[o] += __shfl_xor_sync(0xffffffffu, acc[o], off);
    if (lane == 0) {
#pragma unroll
        for (int o = 0; o < 6; ++o) {
            float v = acc[o];
            float sp = fmaxf(v, 0.f) + log1pf(expf(-fabsf(v)));
            out[(size_t)m * 6 + o] = sp;
        }
    }
}

// ---------------------------------------------------------------------------
extern "C" void kernel_launch(void* const* d_in, const int* in_sizes, int n_in,
                              void* d_out, int out_size)
{
    const float* x   = (const float*)d_in[0];
    const float* W11 = (const float*)d_in[1];
    const float* b11 = (const float*)d_in[2];
    const float* W12 = (const float*)d_in[3];
    const float* W2  = (const float*)d_in[4];
    float* out = (float*)d_out;

    (void)in_sizes; (void)n_in; (void)out_size;

    cudaFuncSetAttribute(k_fc12_mma, cudaFuncAttributeMaxDynamicSharedMemorySize, FC12_SMEM);

    k_fc11<<<MM / 128, 256>>>(x, W11, b11);
    k_prefixmax<<<64, 256>>>();
    k_prepB<<<288, 256>>>(W12);
    k_fc12_mma<<<dim3(MM / 128, 2), 256, FC12_SMEM>>>(x);
    k_ep<<<128, 256>>>();
    k_fc2<<<MM / 8, 256>>>(W2, out);
}

// round 4
// speedup vs baseline: 1.8363x; 1.4182x over previous
#include <cuda_runtime.h>
#include <cuda_bf16.h>
#include <cstdint>

// ---------------------------------------------------------------------------
// Pipeline:
//   S : split x -> bf16 hi/lo             -> g_Ah/g_Al [M,192] (cols 0..127)
//   P1: split W11 (hi|hi|lo)              -> g_B11 [128,384] bf16
//   P2: fold plane-stress D into W12, split -> g_Bp [384,576] bf16
//   A : fc11 mma.sync split GEMM + dnew   -> g_dnew  [M,64]
//   B : prefix-max over T -> dmg, bf16 split -> g_Ah/g_Al cols 128..191
//   C : fc12 mma.sync split GEMM (K'=576) + seq epilogue
//        -> g_strain (= sig_tr) [M,384], g_seq [M,128]
//   E : J2 plasticity scan                -> g_scale [M,128]
//   F : fc2 + softplus                    -> out
// ---------------------------------------------------------------------------

typedef unsigned long long u64;

#define MM 131072   // 256*512

__device__ __align__(16) float g_dnew[(size_t)MM * 64];
__device__ __align__(16) float g_strain[(size_t)MM * 384];
__device__ __align__(16) float g_seq[(size_t)MM * 128];
__device__ __align__(16) float g_scale[(size_t)MM * 128];
__device__ __align__(16) __nv_bfloat16 g_Ah[(size_t)MM * 192];
__device__ __align__(16) __nv_bfloat16 g_Al[(size_t)MM * 192];
__device__ __align__(16) __nv_bfloat16 g_Bp[384 * 576];
__device__ __align__(16) __nv_bfloat16 g_B11[128 * 384];

__device__ __forceinline__ uint32_t smem_u32(const void* p) {
    uint32_t a;
    asm("{ .reg .u64 t; cvta.to.shared.u64 t, %1; cvt.u32.u64 %0, t; }" : "=r"(a) : "l"(p));
    return a;
}
__device__ __forceinline__ void cpasync16(uint32_t dst, const void* src) {
    asm volatile("cp.async.ca.shared.global [%0], [%1], 16;" :: "r"(dst), "l"(src) : "memory");
}
__device__ __forceinline__ void cpcommit() {
    asm volatile("cp.async.commit_group;" ::: "memory");
}
template <int N>
__device__ __forceinline__ void cpwait() {
    asm volatile("cp.async.wait_group %0;" :: "n"(N) : "memory");
}
__device__ __forceinline__ void ldsm_x4(uint32_t& r0, uint32_t& r1, uint32_t& r2,
                                        uint32_t& r3, uint32_t addr) {
    asm volatile("ldmatrix.sync.aligned.m8n8.x4.shared.b16 {%0,%1,%2,%3}, [%4];"
                 : "=r"(r0), "=r"(r1), "=r"(r2), "=r"(r3) : "r"(addr));
}
__device__ __forceinline__ void mma16816(float& c0, float& c1, float& c2, float& c3,
                                         uint32_t a0, uint32_t a1, uint32_t a2, uint32_t a3,
                                         uint32_t b0, uint32_t b1) {
    asm volatile("mma.sync.aligned.m16n8k16.row.col.f32.bf16.bf16.f32 "
                 "{%0,%1,%2,%3}, {%4,%5,%6,%7}, {%8,%9}, {%0,%1,%2,%3};"
                 : "+f"(c0), "+f"(c1), "+f"(c2), "+f"(c3)
                 : "r"(a0), "r"(a1), "r"(a2), "r"(a3), "r"(b0), "r"(b1));
}

#define APITCH 80   // bytes per SMEM row (32 bf16 data + 16B pad)

// ---------------------------------------------------------------------------
// Kernel S: split x into bf16 hi/lo -> g_Ah/g_Al cols [0,128)
// ---------------------------------------------------------------------------
__global__ void k_splitx(const float* __restrict__ x)
{
    int idx = blockIdx.x * 256 + threadIdx.x;     // 0 .. MM*32-1
    int m = idx >> 5, q = (idx & 31) << 2;
    float4 v = *(const float4*)(x + (size_t)m * 128 + q);
    __nv_bfloat16 h[4];
    __nv_bfloat16 l[4];
    float f[4] = {v.x, v.y, v.z, v.w};
#pragma unroll
    for (int i = 0; i < 4; ++i) {
        h[i] = __float2bfloat16(f[i]);
        l[i] = __float2bfloat16(f[i] - __bfloat162float(h[i]));
    }
    *(u64*)(g_Ah + (size_t)m * 192 + q) = *(u64*)h;
    *(u64*)(g_Al + (size_t)m * 192 + q) = *(u64*)l;
}

// ---------------------------------------------------------------------------
// Kernel P1: split W11 -> g_B11 [128,384]: [0,128)=hi, [128,256)=hi, [256,384)=lo
// ---------------------------------------------------------------------------
__global__ void k_prepB11(const float* __restrict__ W11)
{
    int t = blockIdx.x * 256 + threadIdx.x;
    if (t >= 128 * 128) return;
    int n = t >> 7, k = t & 127;
    float w = W11[(size_t)n * 128 + k];
    __nv_bfloat16 hi = __float2bfloat16(w);
    float lo = w - __bfloat162float(hi);
    g_B11[(size_t)n * 384 + k]       = hi;
    g_B11[(size_t)n * 384 + 128 + k] = hi;
    g_B11[(size_t)n * 384 + 256 + k] = __float2bfloat16(lo);
}

// ---------------------------------------------------------------------------
// Kernel P2: fold plane-stress D into W12, split -> g_Bp [384,576]
// ---------------------------------------------------------------------------
__global__ void k_prepB(const float* __restrict__ W12)
{
    int t = blockIdx.x * 256 + threadIdx.x;
    if (t >= 384 * 192) return;
    int n = t / 192, k = t % 192;
    int p3 = (n / 3) * 3, j = n % 3;
    const float C   = 1098.9010989010989f;   // E/(1-nu^2)
    const float CNU = 329.67032967032966f;   // C*nu
    const float CSH = 384.61538461538464f;   // C*(1-nu)/2
    float w;
    if (j == 0)      w = C   * W12[(size_t)p3 * 192 + k] + CNU * W12[(size_t)(p3 + 1) * 192 + k];
    else if (j == 1) w = CNU * W12[(size_t)p3 * 192 + k] + C   * W12[(size_t)(p3 + 1) * 192 + k];
    else             w = CSH * W12[(size_t)n * 192 + k];
    __nv_bfloat16 hi = __float2bfloat16(w);
    float lo = w - __bfloat162float(hi);
    g_Bp[(size_t)n * 576 + k]       = hi;
    g_Bp[(size_t)n * 576 + 192 + k] = hi;
    g_Bp[(size_t)n * 576 + 384 + k] = __float2bfloat16(lo);
}

// ---------------------------------------------------------------------------
// Kernel A: fc11 via mma.sync split GEMM. BM=128, BN=128, K'=384 (12 x Kc=32).
// 256 thr, warp grid 4Mx2N -> warp tile 32x64. cp.async 4-stage pipeline.
// Epilogue: bias + leaky + dnew (fragments hold (even,odd) col pairs).
// smem: 4 stages x (A 128*80 + B 128*80) = 81920
// ---------------------------------------------------------------------------
#define FC11_SMEM 81920

__global__ void __launch_bounds__(256, 1) k_fc11_mma(const float* __restrict__ b11)
{
    extern __shared__ char smem[];
    const uint32_t sb = smem_u32(smem);
    const int tid  = threadIdx.x;
    const int lane = tid & 31;
    const int w    = tid >> 5;
    const int wm   = w >> 1;
    const int wn   = w & 1;
    const int g    = lane >> 2;
    const int t4   = lane & 3;
    const int m0   = blockIdx.x << 7;

    __shared__ float b11s[128];
    if (tid < 128) b11s[tid] = b11[tid];

    float acc[2][8][4];
#pragma unroll
    for (int a = 0; a < 2; ++a)
#pragma unroll
        for (int b = 0; b < 8; ++b)
#pragma unroll
            for (int c = 0; c < 4; ++c) acc[a][b][c] = 0.f;

    const int lrow = tid >> 2, lch = tid & 3;   // A/B load mapping

    // stage issue: stage s -> buffer s&3
    auto issue = [&](int s) {
        const int seg = s >> 2;                 // 0:hi 1:lo 2:hi
        const int kk0 = (s & 3) << 5;
        const __nv_bfloat16* Asrc = (seg == 1) ? g_Al : g_Ah;
        uint32_t base = sb + (uint32_t)(s & 3) * 20480u;
#pragma unroll
        for (int i = 0; i < 2; ++i) {
            int row = lrow + (i << 6);
            cpasync16(base + row * APITCH + (lch << 4),
                      Asrc + (size_t)(m0 + row) * 192 + kk0 + (lch << 3));
        }
#pragma unroll
        for (int i = 0; i < 2; ++i) {
            int row = lrow + (i << 6);
            cpasync16(base + 10240 + row * APITCH + (lch << 4),
                      g_B11 + (size_t)row * 384 + (s << 5) + (lch << 3));
        }
        cpcommit();
    };

    issue(0); issue(1); issue(2);

    for (int s = 0; s < 12; ++s) {
        cpwait<2>();
        __syncthreads();
        if (s + 3 < 12) issue(s + 3);

        const uint32_t Ab = sb + (uint32_t)(s & 3) * 20480u;
        const uint32_t Bb = Ab + 10240u;
#pragma unroll
        for (int ks = 0; ks < 2; ++ks) {
            const int kk = ks << 4;
            uint32_t a[2][4];
#pragma unroll
            for (int mt = 0; mt < 2; ++mt) {
                int row = wm * 32 + mt * 16 + (lane & 15);
                ldsm_x4(a[mt][0], a[mt][1], a[mt][2], a[mt][3],
                        Ab + row * APITCH + ((kk + ((lane >> 4) << 3)) << 1));
            }
#pragma unroll
            for (int np = 0; np < 4; ++np) {
                int n = wn * 64 + np * 16 + ((lane >> 4) << 3) + (lane & 7);
                uint32_t b0, b1, b2, b3;
                ldsm_x4(b0, b1, b2, b3, Bb + n * APITCH + ((kk + (lane & 8)) << 1));
#pragma unroll
                for (int mt = 0; mt < 2; ++mt) {
                    mma16816(acc[mt][2*np][0], acc[mt][2*np][1], acc[mt][2*np][2], acc[mt][2*np][3],
                             a[mt][0], a[mt][1], a[mt][2], a[mt][3], b0, b1);
                    mma16816(acc[mt][2*np+1][0], acc[mt][2*np+1][1], acc[mt][2*np+1][2], acc[mt][2*np+1][3],
                             a[mt][0], a[mt][1], a[mt][2], a[mt][3], b2, b3);
                }
            }
        }
    }

    // epilogue: each fragment holds cols (n, n+1) for rows (r, r+8)
#pragma unroll
    for (int mt = 0; mt < 2; ++mt)
#pragma unroll
        for (int nn = 0; nn < 8; ++nn) {
            int n = wn * 64 + (nn >> 1) * 16 + (nn & 1) * 8 + 2 * t4;
            float be = b11s[n], bo = b11s[n + 1];
            int r0 = m0 + wm * 32 + mt * 16 + g;
#pragma unroll
            for (int hh = 0; hh < 2; ++hh) {
                float v0 = acc[mt][nn][2 * hh]     + be;
                float v1 = acc[mt][nn][2 * hh + 1] + bo;
                v0 = v0 > 0.f ? v0 : 0.01f * v0;
                v1 = v1 > 0.f ? v1 : 0.01f * v1;
                float jn = fmaxf(v0, 0.f);
                float delta = sqrtf(jn * jn + v1 * v1 + 1e-12f);
                float dn = __fdividef(0.1f * (delta - 0.01f),
                                      fmaxf(delta, 1e-12f) * 0.09f);
                dn = fminf(fmaxf(dn, 0.f), 1.f);
                g_dnew[(size_t)(r0 + 8 * hh) * 64 + (n >> 1)] = dn;
            }
        }
}

// ---------------------------------------------------------------------------
// Kernel B: prefix-max of dnew over T; writes dmg as bf16 hi/lo into
// g_Ah/g_Al cols [128,192).
// ---------------------------------------------------------------------------
__global__ void k_prefixmax()
{
    int t = blockIdx.x * blockDim.x + threadIdx.x;   // 0..16383
    int b = t >> 6, p = t & 63;
    const float* src = g_dnew + (size_t)b * 512 * 64 + p;
    __nv_bfloat16* dh = g_Ah + (size_t)b * 512 * 192 + 128 + p;
    __nv_bfloat16* dl = g_Al + (size_t)b * 512 * 192 + 128 + p;
    float run = 0.f;
    for (int t0 = 0; t0 < 512; t0 += 8) {
        float v[8];
#pragma unroll
        for (int i = 0; i < 8; ++i) v[i] = src[(size_t)(t0 + i) * 64];
#pragma unroll
        for (int i = 0; i < 8; ++i) {
            run = fmaxf(run, v[i]);
            __nv_bfloat16 hi = __float2bfloat16(run);
            dh[(size_t)(t0 + i) * 192] = hi;
            dl[(size_t)(t0 + i) * 192] = __float2bfloat16(run - __bfloat162float(hi));
        }
    }
}

// ---------------------------------------------------------------------------
// Kernel C: fc12 via mma.sync split GEMM. grid (1024,2): BM=128, BN=192.
// K'=576 (18 x Kc=32). cp.async 4-stage pipeline. warp tile 32x96.
// Epilogue: acc -> SMEM slab -> seq + coalesced sig_tr/seq stores.
// smem: 4 stages x (A 128*80 + B 192*80) = 102400 (reused as slabs)
// ---------------------------------------------------------------------------
#define FC12_SMEM 102400

__global__ void __launch_bounds__(256, 1) k_fc12_mma()
{
    extern __shared__ char smem[];
    const uint32_t sb = smem_u32(smem);
    const int tid  = threadIdx.x;
    const int lane = tid & 31;
    const int w    = tid >> 5;
    const int wm   = w >> 1;
    const int wn   = w & 1;
    const int g    = lane >> 2;
    const int t4   = lane & 3;
    const int m0   = blockIdx.x << 7;
    const int gy   = blockIdx.y;

    float acc[2][12][4];
#pragma unroll
    for (int a = 0; a < 2; ++a)
#pragma unroll
        for (int b = 0; b < 12; ++b)
#pragma unroll
            for (int c = 0; c < 4; ++c) acc[a][b][c] = 0.f;

    const int lrow = tid >> 2, lch = tid & 3;

    auto issue = [&](int s) {
        const int seg = s / 6;                 // 0:hi 1:lo 2:hi
        const int kk0 = (s % 6) << 5;
        const __nv_bfloat16* Asrc = (seg == 1) ? g_Al : g_Ah;
        uint32_t base = sb + (uint32_t)(s & 3) * 25600u;
#pragma unroll
        for (int i = 0; i < 2; ++i) {
            int row = lrow + (i << 6);
            cpasync16(base + row * APITCH + (lch << 4),
                      Asrc + (size_t)(m0 + row) * 192 + kk0 + (lch << 3));
        }
#pragma unroll
        for (int i = 0; i < 3; ++i) {
            int row = lrow + (i << 6);
            cpasync16(base + 10240 + row * APITCH + (lch << 4),
                      g_Bp + (size_t)(gy * 192 + row) * 576 + (s << 5) + (lch << 3));
        }
        cpcommit();
    };

    issue(0); issue(1); issue(2);

    for (int s = 0; s < 18; ++s) {
        cpwait<2>();
        __syncthreads();
        if (s + 3 < 18) issue(s + 3);

        const uint32_t Ab = sb + (uint32_t)(s & 3) * 25600u;
        const uint32_t Bb = Ab + 10240u;
#pragma unroll
        for (int ks = 0; ks < 2; ++ks) {
            const int kk = ks << 4;
            uint32_t a[2][4];
#pragma unroll
            for (int mt = 0; mt < 2; ++mt) {
                int row = wm * 32 + mt * 16 + (lane & 15);
                ldsm_x4(a[mt][0], a[mt][1], a[mt][2], a[mt][3],
                        Ab + row * APITCH + ((kk + ((lane >> 4) << 3)) << 1));
            }
#pragma unroll
            for (int np = 0; np < 6; ++np) {
                int n = wn * 96 + np * 16 + ((lane >> 4) << 3) + (lane & 7);
                uint32_t b0, b1, b2, b3;
                ldsm_x4(b0, b1, b2, b3, Bb + n * APITCH + ((kk + (lane & 8)) << 1));
#pragma unroll
                for (int mt = 0; mt < 2; ++mt) {
                    mma16816(acc[mt][2*np][0], acc[mt][2*np][1], acc[mt][2*np][2], acc[mt][2*np][3],
                             a[mt][0], a[mt][1], a[mt][2], a[mt][3], b0, b1);
                    mma16816(acc[mt][2*np+1][0], acc[mt][2*np+1][1], acc[mt][2*np+1][2], acc[mt][2*np+1][3],
                             a[mt][0], a[mt][1], a[mt][2], a[mt][3], b2, b3);
                }
            }
        }
    }

    // ---------------- epilogue ----------------
    cpwait<0>();
    __syncthreads();
    float* slab = (float*)smem + w * 3200;     // 32 x 100 floats per warp
#pragma unroll
    for (int mt = 0; mt < 2; ++mt)
#pragma unroll
        for (int nn = 0; nn < 12; ++nn) {
            int row = mt * 16 + g;
            int col = nn * 8 + 2 * t4;
            slab[row * 100 + col]           = acc[mt][nn][0];
            slab[row * 100 + col + 1]       = acc[mt][nn][1];
            slab[(row + 8) * 100 + col]     = acc[mt][nn][2];
            slab[(row + 8) * 100 + col + 1] = acc[mt][nn][3];
        }
    __syncwarp();

    const int mbase = m0 + wm * 32;
    const int cb = gy * 192 + wn * 96;
    const int pbi = gy * 64 + wn * 32;
#pragma unroll 1
    for (int r = 0; r < 32; ++r) {
        float s0 = slab[r * 100 + 3 * lane];
        float s1 = slab[r * 100 + 3 * lane + 1];
        float s2 = slab[r * 100 + 3 * lane + 2];
        float seq = sqrtf(s0 * s0 - s0 * s1 + s1 * s1 + 3.f * s2 * s2 + 1e-12f);
        g_seq[(size_t)(mbase + r) * 128 + pbi + lane] = seq;
        if (lane < 24) {
            float4 v = *(float4*)&slab[r * 100 + 4 * lane];
            *(float4*)&g_strain[(size_t)(mbase + r) * 384 + cb + 4 * lane] = v;
        }
    }
}

// ---------------------------------------------------------------------------
// Kernel E: J2 radial-return ep chains (8-wide load batching for MLP)
// ---------------------------------------------------------------------------
__global__ void k_ep()
{
    int t = blockIdx.x * 256 + threadIdx.x;
    int b = t >> 7, p = t & 127;
    const float* sq = g_seq   + (size_t)b * 512 * 128 + p;
    float*       sc = g_scale + (size_t)b * 512 * 128 + p;
    const float SY = 10.f, H = 100.f;
    const float INV = (float)(1.0 / (3.0 * (1000.0 / 2.6) + 100.0));
    float ep = 0.f;
    for (int t0 = 0; t0 < 512; t0 += 8) {
        float v[8];
#pragma unroll
        for (int i = 0; i < 8; ++i) v[i] = sq[(size_t)(t0 + i) * 128];
        float out[8];
#pragma unroll
        for (int i = 0; i < 8; ++i) {
            float fy = v[i] - fmaf(H, ep, SY);
            if (fy > 0.f) {
                ep = fmaf(fy, INV, ep);
                out[i] = __fdividef(fmaf(H, ep, SY), v[i]);
            } else {
                out[i] = 1.f;
            }
        }
#pragma unroll
        for (int i = 0; i < 8; ++i) sc[(size_t)(t0 + i) * 128] = out[i];
    }
}

// ---------------------------------------------------------------------------
// Kernel F: fc2 + softplus
// ---------------------------------------------------------------------------
__global__ void k_fc2(const float* __restrict__ W2, float* __restrict__ out)
{
    __shared__ float w2s[6 * 384];
    int tid = threadIdx.x;
    for (int i = tid; i < 2304; i += 256) w2s[i] = W2[i];
    __syncthreads();

    int warp = tid >> 5, lane = tid & 31;
    int m = blockIdx.x * 8 + warp;
    const float* sig = g_strain + (size_t)m * 384;
    const float* scl = g_scale  + (size_t)m * 128;
    float acc[6] = {0.f, 0.f, 0.f, 0.f, 0.f, 0.f};
#pragma unroll
    for (int q = 0; q < 4; ++q) {
        int p = lane + 32 * q;
        float s = scl[p];
        float f0 = sig[3 * p], f1 = sig[3 * p + 1], f2 = sig[3 * p + 2];
        float g0 = s * f0, g1 = s * f1, g2 = s * f2;
#pragma unroll
        for (int o = 0; o < 6; ++o) {
            acc[o] = fmaf(g0, w2s[o * 384 + 3 * p],     acc[o]);
            acc[o] = fmaf(g1, w2s[o * 384 + 3 * p + 1], acc[o]);
            acc[o] = fmaf(g2, w2s[o * 384 + 3 * p + 2], acc[o]);
        }
    }
#pragma unroll
    for (int o = 0; o < 6; ++o)
#pragma unroll
        for (int off = 16; off; off >>= 1)
            acc[o] += __shfl_xor_sync(0xffffffffu, acc[o], off);
    if (lane == 0) {
#pragma unroll
        for (int o = 0; o < 6; ++o) {
            float v = acc[o];
            float sp = fmaxf(v, 0.f) + log1pf(expf(-fabsf(v)));
            out[(size_t)m * 6 + o] = sp;
        }
    }
}

// ---------------------------------------------------------------------------
extern "C" void kernel_launch(void* const* d_in, const int* in_sizes, int n_in,
                              void* d_out, int out_size)
{
    const float* x   = (const float*)d_in[0];
    const float* W11 = (const float*)d_in[1];
    const float* b11 = (const float*)d_in[2];
    const float* W12 = (const float*)d_in[3];
    const float* W2  = (const float*)d_in[4];
    float* out = (float*)d_out;

    (void)in_sizes; (void)n_in; (void)out_size;

    cudaFuncSetAttribute(k_fc11_mma, cudaFuncAttributeMaxDynamicSharedMemorySize, FC11_SMEM);
    cudaFuncSetAttribute(k_fc12_mma, cudaFuncAttributeMaxDynamicSharedMemorySize, FC12_SMEM);

    k_splitx<<<MM / 8, 256>>>(x);
    k_prepB11<<<64, 256>>>(W11);
    k_prepB<<<288, 256>>>(W12);
    k_fc11_mma<<<MM / 128, 256, FC11_SMEM>>>(b11);
    k_prefixmax<<<64, 256>>>();
    k_fc12_mma<<<dim3(MM / 128, 2), 256, FC12_SMEM>>>();
    k_ep<<<128, 256>>>();
    k_fc2<<<MM / 8, 256>>>(W2, out);
}

// round 5
// speedup vs baseline: 1.9005x; 1.0349x over previous
#include <cuda_runtime.h>
#include <cuda_bf16.h>
#include <cstdint>

// ---------------------------------------------------------------------------
// Pipeline:
//   S : split x -> bf16 hi/lo             -> g_Ah/g_Al [M,192] (cols 0..127)
//   P1: split W11 (hi|hi|lo)              -> g_B11 [128,384] bf16
//   P2: fold plane-stress D into W12, split -> g_Bp [384,576] bf16
//   A : fc11 mma.sync split GEMM + dnew   -> g_dnew  [M,64]
//   B : prefix-max over T -> dmg, bf16 split -> g_Ah/g_Al cols 128..191
//   C : fc12 mma.sync split GEMM (K'=576) + seq epilogue
//        -> g_strain (= sig_tr) [M,384], g_seq [M,128]
//   E : J2 plasticity scan                -> g_scale [M,128]
//   F : fc2 + softplus                    -> out
// Round-5 change: 3-stage pipelines + smaller BN so both GEMMs run
// 2 CTAs/SM (occ 12.5% -> 25%) to lift tensor-pipe utilization.
// ---------------------------------------------------------------------------

typedef unsigned long long u64;

#define MM 131072   // 256*512

__device__ __align__(16) float g_dnew[(size_t)MM * 64];
__device__ __align__(16) float g_strain[(size_t)MM * 384];
__device__ __align__(16) float g_seq[(size_t)MM * 128];
__device__ __align__(16) float g_scale[(size_t)MM * 128];
__device__ __align__(16) __nv_bfloat16 g_Ah[(size_t)MM * 192];
__device__ __align__(16) __nv_bfloat16 g_Al[(size_t)MM * 192];
__device__ __align__(16) __nv_bfloat16 g_Bp[384 * 576];
__device__ __align__(16) __nv_bfloat16 g_B11[128 * 384];

__device__ __forceinline__ uint32_t smem_u32(const void* p) {
    uint32_t a;
    asm("{ .reg .u64 t; cvta.to.shared.u64 t, %1; cvt.u32.u64 %0, t; }" : "=r"(a) : "l"(p));
    return a;
}
__device__ __forceinline__ void cpasync16(uint32_t dst, const void* src) {
    asm volatile("cp.async.ca.shared.global [%0], [%1], 16;" :: "r"(dst), "l"(src) : "memory");
}
__device__ __forceinline__ void cpcommit() {
    asm volatile("cp.async.commit_group;" ::: "memory");
}
template <int N>
__device__ __forceinline__ void cpwait() {
    asm volatile("cp.async.wait_group %0;" :: "n"(N) : "memory");
}
__device__ __forceinline__ void ldsm_x4(uint32_t& r0, uint32_t& r1, uint32_t& r2,
                                        uint32_t& r3, uint32_t addr) {
    asm volatile("ldmatrix.sync.aligned.m8n8.x4.shared.b16 {%0,%1,%2,%3}, [%4];"
                 : "=r"(r0), "=r"(r1), "=r"(r2), "=r"(r3) : "r"(addr));
}
__device__ __forceinline__ void mma16816(float& c0, float& c1, float& c2, float& c3,
                                         uint32_t a0, uint32_t a1, uint32_t a2, uint32_t a3,
                                         uint32_t b0, uint32_t b1) {
    asm volatile("mma.sync.aligned.m16n8k16.row.col.f32.bf16.bf16.f32 "
                 "{%0,%1,%2,%3}, {%4,%5,%6,%7}, {%8,%9}, {%0,%1,%2,%3};"
                 : "+f"(c0), "+f"(c1), "+f"(c2), "+f"(c3)
                 : "r"(a0), "r"(a1), "r"(a2), "r"(a3), "r"(b0), "r"(b1));
}

#define APITCH 80   // bytes per SMEM row (32 bf16 data + 16B pad)

// ---------------------------------------------------------------------------
// Kernel S: split x into bf16 hi/lo -> g_Ah/g_Al cols [0,128)
// ---------------------------------------------------------------------------
__global__ void k_splitx(const float* __restrict__ x)
{
    int idx = blockIdx.x * 256 + threadIdx.x;     // 0 .. MM*32-1
    int m = idx >> 5, q = (idx & 31) << 2;
    float4 v = *(const float4*)(x + (size_t)m * 128 + q);
    __nv_bfloat16 h[4];
    __nv_bfloat16 l[4];
    float f[4] = {v.x, v.y, v.z, v.w};
#pragma unroll
    for (int i = 0; i < 4; ++i) {
        h[i] = __float2bfloat16(f[i]);
        l[i] = __float2bfloat16(f[i] - __bfloat162float(h[i]));
    }
    *(u64*)(g_Ah + (size_t)m * 192 + q) = *(u64*)h;
    *(u64*)(g_Al + (size_t)m * 192 + q) = *(u64*)l;
}

// ---------------------------------------------------------------------------
// Kernel P1: split W11 -> g_B11 [128,384]: [0,128)=hi, [128,256)=hi, [256,384)=lo
// ---------------------------------------------------------------------------
__global__ void k_prepB11(const float* __restrict__ W11)
{
    int t = blockIdx.x * 256 + threadIdx.x;
    if (t >= 128 * 128) return;
    int n = t >> 7, k = t & 127;
    float w = W11[(size_t)n * 128 + k];
    __nv_bfloat16 hi = __float2bfloat16(w);
    float lo = w - __bfloat162float(hi);
    g_B11[(size_t)n * 384 + k]       = hi;
    g_B11[(size_t)n * 384 + 128 + k] = hi;
    g_B11[(size_t)n * 384 + 256 + k] = __float2bfloat16(lo);
}

// ---------------------------------------------------------------------------
// Kernel P2: fold plane-stress D into W12, split -> g_Bp [384,576]
// ---------------------------------------------------------------------------
__global__ void k_prepB(const float* __restrict__ W12)
{
    int t = blockIdx.x * 256 + threadIdx.x;
    if (t >= 384 * 192) return;
    int n = t / 192, k = t % 192;
    int p3 = (n / 3) * 3, j = n % 3;
    const float C   = 1098.9010989010989f;   // E/(1-nu^2)
    const float CNU = 329.67032967032966f;   // C*nu
    const float CSH = 384.61538461538464f;   // C*(1-nu)/2
    float w;
    if (j == 0)      w = C   * W12[(size_t)p3 * 192 + k] + CNU * W12[(size_t)(p3 + 1) * 192 + k];
    else if (j == 1) w = CNU * W12[(size_t)p3 * 192 + k] + C   * W12[(size_t)(p3 + 1) * 192 + k];
    else             w = CSH * W12[(size_t)n * 192 + k];
    __nv_bfloat16 hi = __float2bfloat16(w);
    float lo = w - __bfloat162float(hi);
    g_Bp[(size_t)n * 576 + k]       = hi;
    g_Bp[(size_t)n * 576 + 192 + k] = hi;
    g_Bp[(size_t)n * 576 + 384 + k] = __float2bfloat16(lo);
}

// ---------------------------------------------------------------------------
// Kernel A: fc11 via mma.sync split GEMM. BM=128, BN=64, K'=384 (12 x Kc=32).
// grid (1024, 2). 256 thr, warp grid 4Mx2N -> warp tile 32x32.
// 3-stage cp.async pipeline; smem 3 x (A 10240 + B 5120) = 46080 -> 2 CTA/SM.
// ---------------------------------------------------------------------------
#define FC11_STAGE 15360
#define FC11_SMEM  46080

__global__ void __launch_bounds__(256, 2) k_fc11_mma(const float* __restrict__ b11)
{
    extern __shared__ char smem[];
    const uint32_t sb = smem_u32(smem);
    const int tid  = threadIdx.x;
    const int lane = tid & 31;
    const int w    = tid >> 5;
    const int wm   = w >> 1;
    const int wn   = w & 1;
    const int g    = lane >> 2;
    const int t4   = lane & 3;
    const int m0   = blockIdx.x << 7;
    const int n0   = blockIdx.y << 6;     // 0 or 64

    __shared__ float b11s[128];
    if (tid < 128) b11s[tid] = b11[tid];

    float acc[2][4][4];
#pragma unroll
    for (int a = 0; a < 2; ++a)
#pragma unroll
        for (int b = 0; b < 4; ++b)
#pragma unroll
            for (int c = 0; c < 4; ++c) acc[a][b][c] = 0.f;

    const int lrow = tid >> 2, lch = tid & 3;

    auto issue = [&](int s) {
        const int seg = s >> 2;                 // 0:hi 1:lo 2:hi
        const int kk0 = (s & 3) << 5;
        const __nv_bfloat16* Asrc = (seg == 1) ? g_Al : g_Ah;
        uint32_t base = sb + (uint32_t)(s % 3) * FC11_STAGE;
#pragma unroll
        for (int i = 0; i < 2; ++i) {
            int row = lrow + (i << 6);
            cpasync16(base + row * APITCH + (lch << 4),
                      Asrc + (size_t)(m0 + row) * 192 + kk0 + (lch << 3));
        }
        // B: 64 rows x 4 chunks = 256 -> one per thread
        cpasync16(base + 10240 + lrow * APITCH + (lch << 4),
                  g_B11 + (size_t)(n0 + lrow) * 384 + (s << 5) + (lch << 3));
        cpcommit();
    };

    issue(0); issue(1);

    for (int s = 0; s < 12; ++s) {
        cpwait<1>();
        __syncthreads();
        if (s + 2 < 12) issue(s + 2);

        const uint32_t Ab = sb + (uint32_t)(s % 3) * FC11_STAGE;
        const uint32_t Bb = Ab + 10240u;
#pragma unroll
        for (int ks = 0; ks < 2; ++ks) {
            const int kk = ks << 4;
            uint32_t a[2][4];
#pragma unroll
            for (int mt = 0; mt < 2; ++mt) {
                int row = wm * 32 + mt * 16 + (lane & 15);
                ldsm_x4(a[mt][0], a[mt][1], a[mt][2], a[mt][3],
                        Ab + row * APITCH + ((kk + ((lane >> 4) << 3)) << 1));
            }
#pragma unroll
            for (int np = 0; np < 2; ++np) {
                int n = wn * 32 + np * 16 + ((lane >> 4) << 3) + (lane & 7);
                uint32_t b0, b1, b2, b3;
                ldsm_x4(b0, b1, b2, b3, Bb + n * APITCH + ((kk + (lane & 8)) << 1));
#pragma unroll
                for (int mt = 0; mt < 2; ++mt) {
                    mma16816(acc[mt][2*np][0], acc[mt][2*np][1], acc[mt][2*np][2], acc[mt][2*np][3],
                             a[mt][0], a[mt][1], a[mt][2], a[mt][3], b0, b1);
                    mma16816(acc[mt][2*np+1][0], acc[mt][2*np+1][1], acc[mt][2*np+1][2], acc[mt][2*np+1][3],
                             a[mt][0], a[mt][1], a[mt][2], a[mt][3], b2, b3);
                }
            }
        }
    }

    // epilogue: fragments hold (even,odd) col pairs -> dnew directly
#pragma unroll
    for (int mt = 0; mt < 2; ++mt)
#pragma unroll
        for (int nn = 0; nn < 4; ++nn) {
            int n = n0 + wn * 32 + (nn >> 1) * 16 + (nn & 1) * 8 + 2 * t4;
            float be = b11s[n], bo = b11s[n + 1];
            int r0 = m0 + wm * 32 + mt * 16 + g;
#pragma unroll
            for (int hh = 0; hh < 2; ++hh) {
                float v0 = acc[mt][nn][2 * hh]     + be;
                float v1 = acc[mt][nn][2 * hh + 1] + bo;
                v0 = v0 > 0.f ? v0 : 0.01f * v0;
                v1 = v1 > 0.f ? v1 : 0.01f * v1;
                float jn = fmaxf(v0, 0.f);
                float delta = sqrtf(jn * jn + v1 * v1 + 1e-12f);
                float dn = __fdividef(0.1f * (delta - 0.01f),
                                      fmaxf(delta, 1e-12f) * 0.09f);
                dn = fminf(fmaxf(dn, 0.f), 1.f);
                g_dnew[(size_t)(r0 + 8 * hh) * 64 + (n >> 1)] = dn;
            }
        }
}

// ---------------------------------------------------------------------------
// Kernel B: prefix-max of dnew over T; writes dmg as bf16 hi/lo into
// g_Ah/g_Al cols [128,192).
// ---------------------------------------------------------------------------
__global__ void k_prefixmax()
{
    int t = blockIdx.x * blockDim.x + threadIdx.x;   // 0..16383
    int b = t >> 6, p = t & 63;
    const float* src = g_dnew + (size_t)b * 512 * 64 + p;
    __nv_bfloat16* dh = g_Ah + (size_t)b * 512 * 192 + 128 + p;
    __nv_bfloat16* dl = g_Al + (size_t)b * 512 * 192 + 128 + p;
    float run = 0.f;
    for (int t0 = 0; t0 < 512; t0 += 8) {
        float v[8];
#pragma unroll
        for (int i = 0; i < 8; ++i) v[i] = src[(size_t)(t0 + i) * 64];
#pragma unroll
        for (int i = 0; i < 8; ++i) {
            run = fmaxf(run, v[i]);
            __nv_bfloat16 hi = __float2bfloat16(run);
            dh[(size_t)(t0 + i) * 192] = hi;
            dl[(size_t)(t0 + i) * 192] = __float2bfloat16(run - __bfloat162float(hi));
        }
    }
}

// ---------------------------------------------------------------------------
// Kernel C: fc12 via mma.sync split GEMM. grid (1024,4): BM=128, BN=96.
// K'=576 (18 x Kc=32). 3-stage cp.async; smem 3 x (10240 + 7680) = 53760
// -> 2 CTA/SM. 8 warps, warp grid 4Mx2N: warp tile 32x48.
// Epilogue: acc -> SMEM slab (32x52/warp) -> seq + coalesced stores.
// ---------------------------------------------------------------------------
#define FC12_STAGE 17920
#define FC12_SMEM  53760

__global__ void __launch_bounds__(256, 2) k_fc12_mma()
{
    extern __shared__ char smem[];
    const uint32_t sb = smem_u32(smem);
    const int tid  = threadIdx.x;
    const int lane = tid & 31;
    const int w    = tid >> 5;
    const int wm   = w >> 1;
    const int wn   = w & 1;
    const int g    = lane >> 2;
    const int t4   = lane & 3;
    const int m0   = blockIdx.x << 7;
    const int gy   = blockIdx.y;          // n-tile: cols gy*96..

    float acc[2][6][4];
#pragma unroll
    for (int a = 0; a < 2; ++a)
#pragma unroll
        for (int b = 0; b < 6; ++b)
#pragma unroll
            for (int c = 0; c < 4; ++c) acc[a][b][c] = 0.f;

    const int lrow = tid >> 2, lch = tid & 3;

    auto issue = [&](int s) {
        const int seg = s / 6;                 // 0:hi 1:lo 2:hi
        const int kk0 = (s % 6) << 5;
        const __nv_bfloat16* Asrc = (seg == 1) ? g_Al : g_Ah;
        uint32_t base = sb + (uint32_t)(s % 3) * FC12_STAGE;
#pragma unroll
        for (int i = 0; i < 2; ++i) {
            int row = lrow + (i << 6);
            cpasync16(base + row * APITCH + (lch << 4),
                      Asrc + (size_t)(m0 + row) * 192 + kk0 + (lch << 3));
        }
        // B: 96 rows x 4 chunks = 384 -> threads 0..255 take 1, 0..127 take 2nd
#pragma unroll
        for (int i = 0; i < 2; ++i) {
            int id = tid + (i << 8);
            if (id < 384) {
                int row = id >> 2, c = id & 3;
                cpasync16(base + 10240 + row * APITCH + (c << 4),
                          g_Bp + (size_t)(gy * 96 + row) * 576 + (s << 5) + (c << 3));
            }
        }
        cpcommit();
    };

    issue(0); issue(1);

    for (int s = 0; s < 18; ++s) {
        cpwait<1>();
        __syncthreads();
        if (s + 2 < 18) issue(s + 2);

        const uint32_t Ab = sb + (uint32_t)(s % 3) * FC12_STAGE;
        const uint32_t Bb = Ab + 10240u;
#pragma unroll
        for (int ks = 0; ks < 2; ++ks) {
            const int kk = ks << 4;
            uint32_t a[2][4];
#pragma unroll
            for (int mt = 0; mt < 2; ++mt) {
                int row = wm * 32 + mt * 16 + (lane & 15);
                ldsm_x4(a[mt][0], a[mt][1], a[mt][2], a[mt][3],
                        Ab + row * APITCH + ((kk + ((lane >> 4) << 3)) << 1));
            }
#pragma unroll
            for (int np = 0; np < 3; ++np) {
                int n = wn * 48 + np * 16 + ((lane >> 4) << 3) + (lane & 7);
                uint32_t b0, b1, b2, b3;
                ldsm_x4(b0, b1, b2, b3, Bb + n * APITCH + ((kk + (lane & 8)) << 1));
#pragma unroll
                for (int mt = 0; mt < 2; ++mt) {
                    mma16816(acc[mt][2*np][0], acc[mt][2*np][1], acc[mt][2*np][2], acc[mt][2*np][3],
                             a[mt][0], a[mt][1], a[mt][2], a[mt][3], b0, b1);
                    mma16816(acc[mt][2*np+1][0], acc[mt][2*np+1][1], acc[mt][2*np+1][2], acc[mt][2*np+1][3],
                             a[mt][0], a[mt][1], a[mt][2], a[mt][3], b2, b3);
                }
            }
        }
    }

    // ---------------- epilogue ----------------
    cpwait<0>();
    __syncthreads();
    float* slab = (float*)smem + w * 1664;     // 32 x 52 floats per warp
#pragma unroll
    for (int mt = 0; mt < 2; ++mt)
#pragma unroll
        for (int nn = 0; nn < 6; ++nn) {
            int row = mt * 16 + g;
            int col = nn * 8 + 2 * t4;
            slab[row * 52 + col]           = acc[mt][nn][0];
            slab[row * 52 + col + 1]       = acc[mt][nn][1];
            slab[(row + 8) * 52 + col]     = acc[mt][nn][2];
            slab[(row + 8) * 52 + col + 1] = acc[mt][nn][3];
        }
    __syncwarp();

    const int mbase = m0 + wm * 32;
    const int cb  = gy * 96 + wn * 48;
    const int pbi = gy * 32 + wn * 16;
#pragma unroll 1
    for (int r = 0; r < 32; ++r) {
        if (lane < 16) {
            float s0 = slab[r * 52 + 3 * lane];
            float s1 = slab[r * 52 + 3 * lane + 1];
            float s2 = slab[r * 52 + 3 * lane + 2];
            float seq = sqrtf(s0 * s0 - s0 * s1 + s1 * s1 + 3.f * s2 * s2 + 1e-12f);
            g_seq[(size_t)(mbase + r) * 128 + pbi + lane] = seq;
        }
        if (lane < 12) {
            float4 v = *(float4*)&slab[r * 52 + 4 * lane];
            *(float4*)&g_strain[(size_t)(mbase + r) * 384 + cb + 4 * lane] = v;
        }
    }
}

// ---------------------------------------------------------------------------
// Kernel E: J2 radial-return ep chains (8-wide load batching for MLP)
// ---------------------------------------------------------------------------
__global__ void k_ep()
{
    int t = blockIdx.x * 256 + threadIdx.x;
    int b = t >> 7, p = t & 127;
    const float* sq = g_seq   + (size_t)b * 512 * 128 + p;
    float*       sc = g_scale + (size_t)b * 512 * 128 + p;
    const float SY = 10.f, H = 100.f;
    const float INV = (float)(1.0 / (3.0 * (1000.0 / 2.6) + 100.0));
    float ep = 0.f;
    for (int t0 = 0; t0 < 512; t0 += 8) {
        float v[8];
#pragma unroll
        for (int i = 0; i < 8; ++i) v[i] = sq[(size_t)(t0 + i) * 128];
        float out[8];
#pragma unroll
        for (int i = 0; i < 8; ++i) {
            float fy = v[i] - fmaf(H, ep, SY);
            if (fy > 0.f) {
                ep = fmaf(fy, INV, ep);
                out[i] = __fdividef(fmaf(H, ep, SY), v[i]);
            } else {
                out[i] = 1.f;
            }
        }
#pragma unroll
        for (int i = 0; i < 8; ++i) sc[(size_t)(t0 + i) * 128] = out[i];
    }
}

// ---------------------------------------------------------------------------
// Kernel F: fc2 + softplus
// ---------------------------------------------------------------------------
__global__ void k_fc2(const float* __restrict__ W2, float* __restrict__ out)
{
    __shared__ float w2s[6 * 384];
    int tid = threadIdx.x;
    for (int i = tid; i < 2304; i += 256) w2s[i] = W2[i];
    __syncthreads();

    int warp = tid >> 5, lane = tid & 31;
    int m = blockIdx.x * 8 + warp;
    const float* sig = g_strain + (size_t)m * 384;
    const float* scl = g_scale  + (size_t)m * 128;
    float acc[6] = {0.f, 0.f, 0.f, 0.f, 0.f, 0.f};
#pragma unroll
    for (int q = 0; q < 4; ++q) {
        int p = lane + 32 * q;
        float s = scl[p];
        float f0 = sig[3 * p], f1 = sig[3 * p + 1], f2 = sig[3 * p + 2];
        float g0 = s * f0, g1 = s * f1, g2 = s * f2;
#pragma unroll
        for (int o = 0; o < 6; ++o) {
            acc[o] = fmaf(g0, w2s[o * 384 + 3 * p],     acc[o]);
            acc[o] = fmaf(g1, w2s[o * 384 + 3 * p + 1], acc[o]);
            acc[o] = fmaf(g2, w2s[o * 384 + 3 * p + 2], acc[o]);
        }
    }
#pragma unroll
    for (int o = 0; o < 6; ++o)
#pragma unroll
        for (int off = 16; off; off >>= 1)
            acc[o] += __shfl_xor_sync(0xffffffffu, acc[o], off);
    if (lane == 0) {
#pragma unroll
        for (int o = 0; o < 6; ++o) {
            float v = acc[o];
            float sp = fmaxf(v, 0.f) + log1pf(expf(-fabsf(v)));
            out[(size_t)m * 6 + o] = sp;
        }
    }
}

// ---------------------------------------------------------------------------
extern "C" void kernel_launch(void* const* d_in, const int* in_sizes, int n_in,
                              void* d_out, int out_size)
{
    const float* x   = (const float*)d_in[0];
    const float* W11 = (const float*)d_in[1];
    const float* b11 = (const float*)d_in[2];
    const float* W12 = (const float*)d_in[3];
    const float* W2  = (const float*)d_in[4];
    float* out = (float*)d_out;

    (void)in_sizes; (void)n_in; (void)out_size;

    cudaFuncSetAttribute(k_fc11_mma, cudaFuncAttributeMaxDynamicSharedMemorySize, FC11_SMEM);
    cudaFuncSetAttribute(k_fc12_mma, cudaFuncAttributeMaxDynamicSharedMemorySize, FC12_SMEM);

    k_splitx<<<MM / 8, 256>>>(x);
    k_prepB11<<<64, 256>>>(W11);
    k_prepB<<<288, 256>>>(W12);
    k_fc11_mma<<<dim3(MM / 128, 2), 256, FC11_SMEM>>>(b11);
    k_prefixmax<<<64, 256>>>();
    k_fc12_mma<<<dim3(MM / 128, 4), 256, FC12_SMEM>>>();
    k_ep<<<128, 256>>>();
    k_fc2<<<MM / 8, 256>>>(W2, out);
}